// round 12
// baseline (speedup 1.0000x reference)
#include <cuda_runtime.h>
#include <cuda_fp16.h>

// Shapes (fixed by the problem)
#define BB   4
#define CC   128
#define NPTS 8192
#define KNN  16
#define OO   128
#define CNT1 32768.0f                // B*N      (stats count for central channels)
#define CNT2 524288.0f               // B*N*K    (stats count for diff channels)

// Scratch (static device globals — allocation-free per harness rules)
__device__ float g_localT[BB*NPTS*OO];   // (B,N,O) fp32, 16 MB
__device__ uint4 g_edgeS [BB*16*NPTS];   // (B, slice, N) x 16B (8 ch fp16), 8 MB
__device__ float g_acc[512];             // sum_l | sq_l | sum_d | sq_d

// ---------------------------------------------------------------------------
// helpers
// ---------------------------------------------------------------------------
__device__ __forceinline__ unsigned h2u(__half2 h) {
    return *reinterpret_cast<unsigned*>(&h);
}
__device__ __forceinline__ float2 u2f2(unsigned u) {
    return __half22float2(*reinterpret_cast<__half2*>(&u));
}

__device__ __forceinline__ unsigned f2tf32(float x) {
    unsigned y;
    asm("cvt.rna.tf32.f32 %0, %1;" : "=r"(y) : "f"(x));
    return y;
}

__device__ __forceinline__ void mma_tf32(float c[4], const unsigned a[4], const unsigned b[2]) {
    asm("mma.sync.aligned.m16n8k8.row.col.f32.tf32.tf32.f32 "
        "{%0,%1,%2,%3}, {%4,%5,%6,%7}, {%8,%9}, {%0,%1,%2,%3};"
        : "+f"(c[0]), "+f"(c[1]), "+f"(c[2]), "+f"(c[3])
        : "r"(a[0]), "r"(a[1]), "r"(a[2]), "r"(a[3]),
          "r"(b[0]), "r"(b[1]));
}

__device__ __forceinline__ void unpack8(const uint4 ev, float e[8]) {
    const float2 e01 = u2f2(ev.x);
    const float2 e23 = u2f2(ev.y);
    const float2 e45 = u2f2(ev.z);
    const float2 e67 = u2f2(ev.w);
    e[0] = e01.x; e[1] = e01.y; e[2] = e23.x; e[3] = e23.y;
    e[4] = e45.x; e[5] = e45.y; e[6] = e67.x; e[7] = e67.y;
}

// ---------------------------------------------------------------------------
// K1: dual GEMM via tf32 tensor cores (mainloop unchanged from R10/R11).
// Edge epilogue now stores slice-major: g_edgeS[(b,slice,n)] = 8 ch fp16.
// ---------------------------------------------------------------------------
__global__ void __launch_bounds__(256, 2) k_gemm(const float* __restrict__ feat,
                                                 const float* __restrict__ W1,
                                                 const float* __restrict__ W2) {
    __shared__ float smem_s[8448];             // A: [0,4224) floats, B: [4224,8448)
    float* As = smem_s;
    float* Bs = smem_s + 4224;

    const int tid = threadIdx.x;
    if (blockIdx.x == 0) {                     // re-zero stat accumulators every replay
        for (int t = tid; t < 512; t += 256) g_acc[t] = 0.f;
    }
    const int mb = blockIdx.x >> 8;            // 0: W1 -> localT, 1: W2 -> edgeS
    const int b  = (blockIdx.x >> 6) & 3;
    const int n0 = (blockIdx.x & 63) << 7;

    const float* Wsel = mb ? W2 : W1;
    const float* fb   = feat + b * (CC * NPTS) + n0;

    const int wid  = tid >> 5, lane = tid & 31;
    const int wm   = (wid >> 2) << 6;
    const int wn   = (wid & 3) << 5;
    const int g    = lane >> 2;
    const int tig  = lane & 3;

    float acc[4][4][4];
#pragma unroll
    for (int mt = 0; mt < 4; ++mt)
#pragma unroll
        for (int nt = 0; nt < 4; ++nt)
#pragma unroll
            for (int q = 0; q < 4; ++q) acc[mt][nt][q] = 0.f;

    for (int kc = 0; kc < 128; kc += 32) {
        __syncthreads();
#pragma unroll
        for (int t = 0; t < 4; ++t) {
            const int i  = tid + (t << 8);
            const int m  = i >> 3;
            const int jj = i & 7;
            const float4 v = *(const float4*)(Wsel + m * 128 + kc + (jj << 2));
            const int ks   = jj >> 1;
            const int comp = ((m >> 3) & 1) + ((jj & 1) << 1);
            const int base = ((m >> 4) << 3) + (m & 7);
            const float va[4] = {v.x, v.y, v.z, v.w};
#pragma unroll
            for (int c = 0; c < 4; ++c)
                As[((ks * 4 + c) * 66 + base) * 4 + comp] = __uint_as_float(f2tf32(va[c]));
        }
#pragma unroll
        for (int t = 0; t < 4; ++t) {
            const int i  = tid + (t << 8);
            const int r  = i >> 6;
            const int n  = (i & 63) << 1;
            const int kl = ((r >> 2) << 3) + (r & 3);
            const float2 lo = *(const float2*)(fb + (kc + kl)     * NPTS + n);
            const float2 hi = *(const float2*)(fb + (kc + kl + 4) * NPTS + n);
            float4 o;
            o.x = __uint_as_float(f2tf32(lo.x));
            o.y = __uint_as_float(f2tf32(hi.x));
            o.z = __uint_as_float(f2tf32(lo.y));
            o.w = __uint_as_float(f2tf32(hi.y));
            *(float4*)&Bs[(r * 132 + n) * 2] = o;
        }
        __syncthreads();

#pragma unroll
        for (int ks = 0; ks < 4; ++ks) {
            const float4* Arow = (const float4*)As + (ks * 4 + tig) * 66 + ((wm >> 4) << 3) + g;
            const float2* Brow = (const float2*)Bs + (ks * 4 + tig) * 132 + wn + g;

            unsigned afr[4][4], bfr[4][2];
#pragma unroll
            for (int mt = 0; mt < 4; ++mt) {
                const float4 a = Arow[mt << 3];
                afr[mt][0] = __float_as_uint(a.x);
                afr[mt][1] = __float_as_uint(a.y);
                afr[mt][2] = __float_as_uint(a.z);
                afr[mt][3] = __float_as_uint(a.w);
            }
#pragma unroll
            for (int nt = 0; nt < 4; ++nt) {
                const float2 bv = Brow[nt << 3];
                bfr[nt][0] = __float_as_uint(bv.x);
                bfr[nt][1] = __float_as_uint(bv.y);
            }
#pragma unroll
            for (int mt = 0; mt < 4; ++mt)
#pragma unroll
                for (int nt = 0; nt < 4; ++nt)
                    mma_tf32(acc[mt][nt], afr[mt], bfr[nt]);
        }
    }

    // ---- epilogue: per-warp transpose via smem (reuse staging region) ----
    __syncthreads();
    float* wb = smem_s + wid * 544;             // per-warp [8][68]

#pragma unroll
    for (int nt = 0; nt < 4; ++nt) {
        __syncwarp();
#pragma unroll
        for (int mt = 0; mt < 4; ++mt) {
            float* wr0 = wb + (2 * tig) * 68 + (mt << 4) + g;
            float* wr1 = wb + (2 * tig + 1) * 68 + (mt << 4) + g;
            wr0[0] = acc[mt][nt][0];
            wr1[0] = acc[mt][nt][1];
            wr0[8] = acc[mt][nt][2];
            wr1[8] = acc[mt][nt][3];
        }
        __syncwarp();
#pragma unroll
        for (int r = 0; r < 4; ++r) {
            const int j  = lane + (r << 5);
            const int nl = j >> 4;
            const int mq = (j & 15) << 2;
            const float4 v = *(const float4*)&wb[nl * 68 + mq];
            const int n = n0 + wn + (nt << 3) + nl;
            const int p = b * NPTS + n;
            if (mb == 0) {
                *(float4*)&g_localT[((size_t)p << 7) + wm + mq] = v;
            } else {
                uint2 h;
                h.x = h2u(__floats2half2_rn(v.x, v.y));
                h.y = h2u(__floats2half2_rn(v.z, v.w));
                const int ch0 = wm + mq;                 // multiple of 4
                const int s   = ch0 >> 3;
                const int hs  = (ch0 >> 2) & 1;
                ((uint2*)&g_edgeS[((((size_t)b << 4) | s) << 13) + n])[hs] = h;
            }
        }
    }
}

// ---------------------------------------------------------------------------
// K2: BN statistics via smem-resident gather table.
// Block = (batch, 8-ch slice, n-half). Stages full 8192-pt slice table
// (128 KB) in dynamic smem; thread-per-point, serial k, LDS.128 gathers.
// ---------------------------------------------------------------------------
__global__ void __launch_bounds__(512, 1) k_stats(const int* __restrict__ knn) {
    extern __shared__ uint4 tab[];             // [8192] = 128 KB
    __shared__ float sacc[32];

    const int tid  = threadIdx.x;
    const int blk  = blockIdx.x;
    const int b    = blk >> 5;
    const int s    = (blk >> 1) & 15;
    const int half = blk & 1;
    const int c0   = s << 3;

    const uint4* src = g_edgeS + ((((size_t)b << 4) | s) << 13);
    for (int i = tid; i < 8192; i += 512) tab[i] = src[i];
    __syncthreads();

    float sl[8], sql[8], sd[8], sqd[8];
#pragma unroll
    for (int j = 0; j < 8; ++j) { sl[j] = sql[j] = sd[j] = sqd[j] = 0.f; }

    const int n0 = half << 12;
    for (int it = 0; it < 8; ++it) {
        const int p  = n0 + (it << 9) + tid;
        const int gp = (b << 13) + p;
        const float4 l0 = *(const float4*)&g_localT[((size_t)gp << 7) + c0];
        const float4 l1 = *(const float4*)&g_localT[((size_t)gp << 7) + c0 + 4];
        const float l[8] = {l0.x, l0.y, l0.z, l0.w, l1.x, l1.y, l1.z, l1.w};
#pragma unroll
        for (int j = 0; j < 8; ++j) { sl[j] += l[j]; sql[j] += l[j] * l[j]; }

        const int4* kr = (const int4*)(knn + gp * 16);
        const int4 k0 = kr[0], k1 = kr[1], k2 = kr[2], k3 = kr[3];
        const int idx[16] = {k0.x, k0.y, k0.z, k0.w, k1.x, k1.y, k1.z, k1.w,
                             k2.x, k2.y, k2.z, k2.w, k3.x, k3.y, k3.z, k3.w};
#pragma unroll
        for (int k = 0; k < 16; ++k) {
            float e[8];
            unpack8(tab[idx[k]], e);
#pragma unroll
            for (int j = 0; j < 8; ++j) {
                const float d = e[j] - l[j];
                sd[j] += d; sqd[j] += d * d;
            }
        }
    }

    // warp reduce (all lanes hold the same 8 channels)
#pragma unroll
    for (int off = 16; off; off >>= 1) {
#pragma unroll
        for (int j = 0; j < 8; ++j) {
            sl[j]  += __shfl_xor_sync(0xffffffffu, sl[j],  off);
            sql[j] += __shfl_xor_sync(0xffffffffu, sql[j], off);
            sd[j]  += __shfl_xor_sync(0xffffffffu, sd[j],  off);
            sqd[j] += __shfl_xor_sync(0xffffffffu, sqd[j], off);
        }
    }
    if (tid < 32) sacc[tid] = 0.f;
    __syncthreads();
    if ((tid & 31) == 0) {
#pragma unroll
        for (int j = 0; j < 8; ++j) {
            atomicAdd(&sacc[j],      sl[j]);
            atomicAdd(&sacc[8 + j],  sql[j]);
            atomicAdd(&sacc[16 + j], sd[j]);
            atomicAdd(&sacc[24 + j], sqd[j]);
        }
    }
    __syncthreads();
    if (tid < 32) {
        const int j = tid & 7, grp = tid >> 3;   // 0:sl 1:sql 2:sd 3:sqd
        atomicAdd(&g_acc[grp * 128 + c0 + j], sacc[tid]);
    }
}

// ---------------------------------------------------------------------------
// K3: output via the same smem-gather. Thread-per-point, n-contiguous, so the
// (B,256,N) stores are naturally coalesced — no staging needed.
// ---------------------------------------------------------------------------
__global__ void __launch_bounds__(512, 1) k_out(const int* __restrict__ knn,
                                                const float* __restrict__ gamma,
                                                const float* __restrict__ beta,
                                                float* __restrict__ out) {
    extern __shared__ uint4 tab[];             // [8192] = 128 KB
    __shared__ float s_a[16], s_sh[16];

    const int tid  = threadIdx.x;
    const int blk  = blockIdx.x;
    const int b    = blk >> 5;
    const int s    = (blk >> 1) & 15;
    const int half = blk & 1;
    const int c0   = s << 3;

    const uint4* src = g_edgeS + ((((size_t)b << 4) | s) << 13);
    for (int i = tid; i < 8192; i += 512) tab[i] = src[i];

    if (tid < 16) {                            // BN affine params for this slice
        const int j = tid & 7;
        const bool central = tid < 8;
        const int ch = central ? (c0 + j) : (128 + c0 + j);
        const float sum = central ? g_acc[c0 + j]       : g_acc[256 + c0 + j];
        const float sq  = central ? g_acc[128 + c0 + j] : g_acc[384 + c0 + j];
        const float inv = central ? (1.f / CNT1) : (1.f / CNT2);
        const float mean = sum * inv;
        const float var  = fmaxf(sq * inv - mean * mean, 0.f);
        const float a    = gamma[ch] * rsqrtf(var + 1e-5f);
        s_a[tid]  = a;
        s_sh[tid] = beta[ch] - a * mean;
    }
    __syncthreads();

    float a1[8], sh1[8], a2[8], sh2[8];
#pragma unroll
    for (int j = 0; j < 8; ++j) {
        a1[j] = s_a[j];     sh1[j] = s_sh[j];
        a2[j] = s_a[8 + j]; sh2[j] = s_sh[8 + j];
    }

    const int n0 = half << 12;
    for (int it = 0; it < 8; ++it) {
        const int p  = n0 + (it << 9) + tid;
        const int gp = (b << 13) + p;
        const float4 l0 = *(const float4*)&g_localT[((size_t)gp << 7) + c0];
        const float4 l1 = *(const float4*)&g_localT[((size_t)gp << 7) + c0 + 4];
        const float l[8] = {l0.x, l0.y, l0.z, l0.w, l1.x, l1.y, l1.z, l1.w};

        const int4* kr = (const int4*)(knn + gp * 16);
        const int4 k0 = kr[0], k1 = kr[1], k2 = kr[2], k3 = kr[3];
        const int idx[16] = {k0.x, k0.y, k0.z, k0.w, k1.x, k1.y, k1.z, k1.w,
                             k2.x, k2.y, k2.z, k2.w, k3.x, k3.y, k3.z, k3.w};

        float accf[8];
#pragma unroll
        for (int j = 0; j < 8; ++j) accf[j] = 0.f;
#pragma unroll
        for (int k = 0; k < 16; ++k) {
            float e[8];
            unpack8(tab[idx[k]], e);
#pragma unroll
            for (int j = 0; j < 8; ++j)
                accf[j] += fmaxf(a2[j] * (e[j] - l[j]) + sh2[j], 0.f);
        }

        // coalesced stores: consecutive tid -> consecutive n
        float* ob = out + ((size_t)b << 21) + p;   // b*256*8192 + n
#pragma unroll
        for (int j = 0; j < 8; ++j) {
            ob[(size_t)(c0 + j) * NPTS]        = fmaxf(a1[j] * l[j] + sh1[j], 0.f);
            ob[(size_t)(128 + c0 + j) * NPTS]  = accf[j] * (1.f / 16.f);
        }
    }
}

// ---------------------------------------------------------------------------
extern "C" void kernel_launch(void* const* d_in, const int* in_sizes, int n_in,
                              void* d_out, int out_size) {
    const float* feat  = (const float*)d_in[0];
    const int*   knn   = (const int*)  d_in[1];
    const float* W1    = (const float*)d_in[2];
    const float* W2    = (const float*)d_in[3];
    const float* gamma = (const float*)d_in[4];
    const float* beta  = (const float*)d_in[5];
    float* out = (float*)d_out;

    const int TAB_BYTES = 8192 * 16;           // 128 KB dynamic smem
    cudaFuncSetAttribute(k_stats, cudaFuncAttributeMaxDynamicSharedMemorySize, TAB_BYTES);
    cudaFuncSetAttribute(k_out,   cudaFuncAttributeMaxDynamicSharedMemorySize, TAB_BYTES);

    k_gemm <<<512, 256>>>(feat, W1, W2);
    k_stats<<<128, 512, TAB_BYTES>>>(knn);
    k_out  <<<128, 512, TAB_BYTES>>>(knn, gamma, beta, out);
}